// round 1
// baseline (speedup 1.0000x reference)
#include <cuda_runtime.h>

#define NROWS 8192
#define DDIM  8192
#define KIN   1024
#define NTHREADS 256

typedef unsigned long long ull;

// ---- packed f32x2 helpers (Blackwell sm_103a) ----
__device__ __forceinline__ ull pack2(float lo, float hi) {
    ull r; asm("mov.b64 %0, {%1, %2};" : "=l"(r) : "f"(lo), "f"(hi)); return r;
}
__device__ __forceinline__ void unpack2(ull v, float& lo, float& hi) {
    asm("mov.b64 {%0, %1}, %2;" : "=f"(lo), "=f"(hi) : "l"(v));
}
__device__ __forceinline__ ull f2add(ull a, ull b) {
    ull r; asm("add.rn.f32x2 %0, %1, %2;" : "=l"(r) : "l"(a), "l"(b)); return r;
}
// a - b  ==  fma(b, -1, a)   (no sub.f32x2 dependence)
__device__ __forceinline__ ull f2sub(ull a, ull b) {
    const ull NEG1 = 0xBF800000BF800000ULL;  // (-1.f, -1.f)
    ull r; asm("fma.rn.f32x2 %0, %1, %2, %3;" : "=l"(r) : "l"(b), "l"(NEG1), "l"(a)); return r;
}
__device__ __forceinline__ ull f2mul(ull a, ull b) {
    ull r; asm("mul.rn.f32x2 %0, %1, %2;" : "=l"(r) : "l"(a), "l"(b)); return r;
}

// Bank-conflict-avoiding storage swizzle (analyzed per-phase; see notes).
__device__ __forceinline__ int sw_full(int e) {
    return e ^ ((e >> 5) & 7) ^ (((e >> 8) & 3) << 3);
}

// Packed Hadamard over 16 x f32x2 (covers 4 bits; the 5th bit was folded at pack time)
__device__ __forceinline__ void h16_packed(ull* y) {
#pragma unroll
    for (int m = 8; m >= 1; m >>= 1) {
#pragma unroll
        for (int j = 0; j < 16; j++) {
            if ((j & m) == 0) {
                ull a = y[j], b = y[j | m];
                y[j]     = f2add(a, b);
                y[j | m] = f2sub(a, b);
            }
        }
    }
}

__global__ void __launch_bounds__(NTHREADS, 2) fwht_kernel(
    const float* __restrict__ u, const int* __restrict__ idx, float* __restrict__ out)
{
    __shared__ float sm[DDIM];
    const int t   = threadIdx.x;
    const int row = blockIdx.x;
    const int l   = t & 31;   // lane
    const int wp  = t >> 5;   // warp (0..7)

    // ---- zero smem (32KB, vectorized, conflict-free) ----
    float4* sm4 = reinterpret_cast<float4*>(sm);
    const float4 z4 = make_float4(0.f, 0.f, 0.f, 0.f);
#pragma unroll
    for (int i = 0; i < DDIM / 4 / NTHREADS; i++) sm4[t + NTHREADS * i] = z4;
    __syncthreads();

    // ---- scatter u into swizzled smem (idx may contain duplicates -> atomicAdd) ----
    const float* urow = u + (long)row * KIN;
#pragma unroll
    for (int kk = 0; kk < KIN / NTHREADS; kk++) {
        int k = t + NTHREADS * kk;
        atomicAdd(&sm[sw_full(idx[k])], urow[k]);
    }
    __syncthreads();

    ull y[16];

    // ==== Phase 1: Hadamard over e-bits 5..9 (strides 32..512) in registers ====
    // thread owns e = l + 32*r + 1024*wp, r=0..31; swizzled addr = 1024*wp + 32*r + (l^r)
    {
        const int b1 = wp << 10;
#pragma unroll
        for (int i = 0; i < 16; i++) {
            float a = sm[b1 + 32 * i        + (l ^ i)];
            float b = sm[b1 + 32 * (i + 16) + (l ^ (i + 16))];
            y[i] = pack2(a + b, a - b);   // stage for r-bit 4 fused into packing
        }
        h16_packed(y);                     // r-bits 0..3
        // exclusive per-thread addresses: no sync needed between read and write
#pragma unroll
        for (int i = 0; i < 16; i++) {
            float lo, hi; unpack2(y[i], lo, hi);
            sm[b1 + 32 * i        + (l ^ i)]        = lo;
            sm[b1 + 32 * (i + 16) + (l ^ (i + 16))] = hi;
        }
    }
    __syncthreads();

    // ==== Phase 2: Hadamard over e-bits 0..4 (strides 1..16) in registers ====
    // thread owns e = v + 32*l + 1024*wp, v=0..31; swizzled addr = b2 + (v^l)
    {
        const int b2 = (wp << 10) + (l << 5);
#pragma unroll
        for (int i = 0; i < 16; i++) {
            float a = sm[b2 + (i ^ l)];
            float b = sm[b2 + ((i + 16) ^ l)];
            y[i] = pack2(a + b, a - b);   // bit 4 fused
        }
        h16_packed(y);                     // bits 0..3
#pragma unroll
        for (int i = 0; i < 16; i++) {
            float lo, hi; unpack2(y[i], lo, hi);
            sm[b2 + (i ^ l)]        = lo;
            sm[b2 + ((i + 16) ^ l)] = hi;
        }
    }
    __syncthreads();

    // ==== Phase 3: Hadamard over e-bits 10..12 (strides 1024..4096), 4 groups (m) ====
    // thread owns e = l + 32*(wp+8m) + 1024*w  (m=0..3, w=0..7)
    // swizzled addr = (l ^ wp ^ (((m+4w)&3)<<3)) + 32*(wp+8m) + 1024*w
    // Global stores per (m,w): lanes write contiguous 128B -> fully coalesced.
    {
        float* orow = out + (long)row * DDIM;
        const int lxw = l ^ wp;
        // pack: y[w] = (group m=0, m=1), y[8+w] = (group m=2, m=3)
#pragma unroll
        for (int w = 0; w < 8; w++) {
#pragma unroll
            for (int p = 0; p < 2; p++) {
                const int m0 = 2 * p, m1 = 2 * p + 1;
                const int a0 = (lxw ^ (((m0 + 4 * w) & 3) << 3)) + ((wp + 8 * m0) << 5) + (w << 10);
                const int a1 = (lxw ^ (((m1 + 4 * w) & 3) << 3)) + ((wp + 8 * m1) << 5) + (w << 10);
                y[p * 8 + w] = pack2(sm[a0], sm[a1]);
            }
        }
        // H8 over w (both packed lanes are independent groups)
#pragma unroll
        for (int m = 4; m >= 1; m >>= 1) {
#pragma unroll
            for (int j = 0; j < 8; j++) {
                if ((j & m) == 0) {
                    ull a = y[j], b = y[j | m];
                    y[j]     = f2add(a, b);
                    y[j | m] = f2sub(a, b);
                    ull c = y[8 + j], d = y[8 + (j | m)];
                    y[8 + j]       = f2add(c, d);
                    y[8 + (j | m)] = f2sub(c, d);
                }
            }
        }
        // scale by 1/sqrt(8192)
        const float SCALE = 0.011048543456039806f;
        const ull SC2 = pack2(SCALE, SCALE);
#pragma unroll
        for (int i = 0; i < 16; i++) y[i] = f2mul(y[i], SC2);

        // coalesced stores
#pragma unroll
        for (int w = 0; w < 8; w++) {
#pragma unroll
            for (int p = 0; p < 2; p++) {
                float lo, hi; unpack2(y[p * 8 + w], lo, hi);
                orow[l + ((wp + 8 * (2 * p))     << 5) + (w << 10)] = lo;
                orow[l + ((wp + 8 * (2 * p + 1)) << 5) + (w << 10)] = hi;
            }
        }
    }
}

extern "C" void kernel_launch(void* const* d_in, const int* in_sizes, int n_in,
                              void* d_out, int out_size)
{
    const float* u   = (const float*)d_in[0];
    const int*   idx = (const int*)d_in[1];
    float*       out = (float*)d_out;
    fwht_kernel<<<NROWS, NTHREADS>>>(u, idx, out);
}

// round 2
// speedup vs baseline: 1.2696x; 1.2696x over previous
#include <cuda_runtime.h>

#define NROWS 8192
#define DDIM  8192
#define KIN   1024
#define NTHREADS 256

typedef unsigned long long ull;

// ---- packed f32x2 helpers (Blackwell sm_103a) ----
__device__ __forceinline__ ull pack2(float lo, float hi) {
    ull r; asm("mov.b64 %0, {%1, %2};" : "=l"(r) : "f"(lo), "f"(hi)); return r;
}
__device__ __forceinline__ void unpack2(ull v, float& lo, float& hi) {
    asm("mov.b64 {%0, %1}, %2;" : "=f"(lo), "=f"(hi) : "l"(v));
}
__device__ __forceinline__ ull f2add(ull a, ull b) {
    ull r; asm("add.rn.f32x2 %0, %1, %2;" : "=l"(r) : "l"(a), "l"(b)); return r;
}
// a - b == fma(b, -1, a)
__device__ __forceinline__ ull f2sub(ull a, ull b) {
    const ull NEG1 = 0xBF800000BF800000ULL;
    ull r; asm("fma.rn.f32x2 %0, %1, %2, %3;" : "=l"(r) : "l"(b), "l"(NEG1), "l"(a)); return r;
}
__device__ __forceinline__ ull f2mul(ull a, ull b) {
    ull r; asm("mul.rn.f32x2 %0, %1, %2;" : "=l"(r) : "l"(a), "l"(b)); return r;
}

// Bank-conflict-avoiding storage swizzle (conflict-free in all three phases).
__device__ __forceinline__ int sw_full(int e) {
    return e ^ ((e >> 5) & 7) ^ (((e >> 8) & 3) << 3);
}

// Packed Hadamard over 16 x f32x2 (4 bits; 5th bit folded at pack time)
__device__ __forceinline__ void h16_packed(ull* y) {
#pragma unroll
    for (int m = 8; m >= 1; m >>= 1) {
#pragma unroll
        for (int j = 0; j < 16; j++) {
            if ((j & m) == 0) {
                ull a = y[j], b = y[j | m];
                y[j]     = f2add(a, b);
                y[j | m] = f2sub(a, b);
            }
        }
    }
}

__global__ void __launch_bounds__(NTHREADS, 3) fwht_kernel(
    const float* __restrict__ u, const int* __restrict__ idx, float* __restrict__ out)
{
    __shared__ float sm[DDIM];
    const int t   = threadIdx.x;
    const int row = blockIdx.x;
    const int l   = t & 31;   // lane
    const int wp  = t >> 5;   // warp (0..7)

    // ---- zero smem (32KB, vectorized, conflict-free) ----
    float4* sm4 = reinterpret_cast<float4*>(sm);
    const float4 z4 = make_float4(0.f, 0.f, 0.f, 0.f);
#pragma unroll
    for (int i = 0; i < DDIM / 4 / NTHREADS; i++) sm4[t + NTHREADS * i] = z4;
    __syncthreads();

    // ---- scatter u into swizzled smem: idx is SORTED, duplicates are adjacent.
    // Run-leader scheme with plain stores (no atomics). Thread owns k0..k0+3.
    {
        const float* urow = u + (long)row * KIN;
        const int k0 = 4 * t;
        const int4   iv = reinterpret_cast<const int4*>(idx)[t];
        const float4 uv = reinterpret_cast<const float4*>(urow)[t];
        int   id[4] = {iv.x, iv.y, iv.z, iv.w};
        float uu[4] = {uv.x, uv.y, uv.z, uv.w};
        int prev = (t == 0) ? -1 : idx[k0 - 1];
#pragma unroll
        for (int p = 0; p < 4; p++) {
            if (id[p] != prev) {
                float val = uu[p];
                int q = p + 1;
                while (q < 4 && id[q] == id[p]) { val += uu[q]; q++; }
                if (q == 4) {
                    // run may spill into the next quad (rare)
                    int j = k0 + 4;
                    while (j < KIN && idx[j] == id[p]) { val += urow[j]; j++; }
                }
                sm[sw_full(id[p])] = val;
            }
            prev = id[p];
        }
    }
    __syncthreads();

    ull y[16];

    // ==== Phase 1: Hadamard over e-bits 5..9 (strides 32..512) in registers ====
    // thread owns e = l + 32*r + 1024*wp; swizzled addr = 1024*wp + 32*r + (l^r)
    {
        const int b1 = wp << 10;
#pragma unroll
        for (int i = 0; i < 16; i++) {
            float a = sm[b1 + 32 * i        + (l ^ i)];
            float b = sm[b1 + 32 * (i + 16) + (l ^ (i + 16))];
            y[i] = pack2(a + b, a - b);   // r-bit 4 fused into packing
        }
        h16_packed(y);                     // r-bits 0..3
#pragma unroll
        for (int i = 0; i < 16; i++) {
            float lo, hi; unpack2(y[i], lo, hi);
            sm[b1 + 32 * i        + (l ^ i)]        = lo;
            sm[b1 + 32 * (i + 16) + (l ^ (i + 16))] = hi;
        }
    }
    __syncthreads();

    // ==== Phase 2: Hadamard over e-bits 0..4 (strides 1..16) in registers ====
    // thread owns e = v + 32*l + 1024*wp; swizzled addr = b2 + (v^l)
    {
        const int b2 = (wp << 10) + (l << 5);
#pragma unroll
        for (int i = 0; i < 16; i++) {
            float a = sm[b2 + (i ^ l)];
            float b = sm[b2 + ((i + 16) ^ l)];
            y[i] = pack2(a + b, a - b);   // bit 4 fused
        }
        h16_packed(y);                     // bits 0..3
#pragma unroll
        for (int i = 0; i < 16; i++) {
            float lo, hi; unpack2(y[i], lo, hi);
            sm[b2 + (i ^ l)]        = lo;
            sm[b2 + ((i + 16) ^ l)] = hi;
        }
    }
    __syncthreads();

    // ==== Phase 3: Hadamard over e-bits 10..12 (strides 1024..4096), 4 groups ====
    // thread owns e = l + 32*(wp+8m) + 1024*w  (m=0..3, w=0..7)
    // swizzled addr = (l ^ wp ^ (((m+4w)&3)<<3)) + 32*(wp+8m) + 1024*w
    {
        float* orow = out + (long)row * DDIM;
        const int lxw = l ^ wp;
#pragma unroll
        for (int w = 0; w < 8; w++) {
#pragma unroll
            for (int p = 0; p < 2; p++) {
                const int m0 = 2 * p, m1 = 2 * p + 1;
                const int a0 = (lxw ^ (((m0 + 4 * w) & 3) << 3)) + ((wp + 8 * m0) << 5) + (w << 10);
                const int a1 = (lxw ^ (((m1 + 4 * w) & 3) << 3)) + ((wp + 8 * m1) << 5) + (w << 10);
                y[p * 8 + w] = pack2(sm[a0], sm[a1]);
            }
        }
        // H8 over w (both packed lanes are independent groups)
#pragma unroll
        for (int m = 4; m >= 1; m >>= 1) {
#pragma unroll
            for (int j = 0; j < 8; j++) {
                if ((j & m) == 0) {
                    ull a = y[j], b = y[j | m];
                    y[j]     = f2add(a, b);
                    y[j | m] = f2sub(a, b);
                    ull c = y[8 + j], d = y[8 + (j | m)];
                    y[8 + j]       = f2add(c, d);
                    y[8 + (j | m)] = f2sub(c, d);
                }
            }
        }
        // scale by 1/sqrt(8192)
        const float SCALE = 0.011048543456039806f;
        const ull SC2 = pack2(SCALE, SCALE);
#pragma unroll
        for (int i = 0; i < 16; i++) y[i] = f2mul(y[i], SC2);

        // coalesced stores (lane-contiguous 128B segments)
#pragma unroll
        for (int w = 0; w < 8; w++) {
#pragma unroll
            for (int p = 0; p < 2; p++) {
                float lo, hi; unpack2(y[p * 8 + w], lo, hi);
                orow[l + ((wp + 8 * (2 * p))     << 5) + (w << 10)] = lo;
                orow[l + ((wp + 8 * (2 * p + 1)) << 5) + (w << 10)] = hi;
            }
        }
    }
}

extern "C" void kernel_launch(void* const* d_in, const int* in_sizes, int n_in,
                              void* d_out, int out_size)
{
    const float* u   = (const float*)d_in[0];
    const int*   idx = (const int*)d_in[1];
    float*       out = (float*)d_out;
    fwht_kernel<<<NROWS, NTHREADS>>>(u, idx, out);
}